// round 13
// baseline (speedup 1.0000x reference)
#include <cuda_runtime.h>
#include <stdint.h>

// ---------------------------------------------------------------------------
// extract_high_freq via db4 wavelet, [96][512][512] fp32 — single fused kernel.
//   P0: lo_s[i] = row-DWT-approx(data[mir(R0-6+i)]); hi_s for own rows
//   P1: lr_s[tt] = 14-tap column conv of lo_s (fused detail+synthesis+identity)
//   P2: out[t]   = row-IDWT(lr_s[tt], 2*hi_s[tt])   (packed f32x2)
// ---------------------------------------------------------------------------

#define N     512
#define M     259          // (512+7)/2
#define NIMG  96

#define TR    16           // output rows per block
#define LOR   28           // lo rows: global [R0-6, R0+21]
#define KS    260          // smem row stride (floats)

#define DL0 (-0.010597401784997278f)
#define DL1 ( 0.032883011666982945f)
#define DL2 ( 0.030841381835986965f)
#define DL3 (-0.18703481171888114f)
#define DL4 (-0.02798376941698385f)
#define DL5 ( 0.6308807679295904f)
#define DL6 ( 0.7148465705525415f)
#define DL7 ( 0.23037781330885523f)

// REC_LO[j] = DEC_LO[7-j] ; REC_HI[j] = (-1)^j * DEC_LO[j]
#define REC_LO_INIT  { DL7,  DL6,  DL5,  DL4,  DL3,  DL2,  DL1,  DL0 }
#define REC_HI_INIT  { DL0, -DL1,  DL2, -DL3,  DL4, -DL5,  DL6, -DL7 }
#define REC_HI2_INIT { 2*DL0, -2*DL1, 2*DL2, -2*DL3, 2*DL4, -2*DL5, 2*DL6, -2*DL7 }

// Combined column-correction weights (detail ∘ synthesis + identity).
__host__ __device__ constexpr float rh_at(int j) {
    constexpr float rh[8] = REC_HI_INIT;
    return rh[j];
}
__host__ __device__ constexpr float we_at(int m) {  // even t: rows tt..tt+13
    float s = (m == 6) ? 1.0f : 0.0f;
    for (int i = 0; i < 4; ++i) {
        const int j = m - 2 * i;
        if (j >= 0 && j < 8) s += rh_at(6 - 2 * i) * rh_at(j);
    }
    return s;
}
__host__ __device__ constexpr float wo_at(int m) {  // odd t: rows tt-1..tt+12
    float s = (m == 7) ? 1.0f : 0.0f;
    for (int i = 0; i < 4; ++i) {
        const int j = m - 2 * i;
        if (j >= 0 && j < 8) s += rh_at(7 - 2 * i) * rh_at(j);
    }
    return s;
}

// packed f32x2 helpers (sm_100+)
__device__ __forceinline__ unsigned long long pk2(float lo, float hi) {
    unsigned long long r;
    asm("mov.b64 %0, {%1, %2};" : "=l"(r) : "f"(lo), "f"(hi));
    return r;
}
__device__ __forceinline__ void fma2(unsigned long long& d,
                                     unsigned long long a,
                                     unsigned long long b) {
    asm("fma.rn.f32x2 %0, %1, %2, %3;" : "=l"(d) : "l"(a), "l"(b), "l"(d));
}

__device__ __forceinline__ int mirN(int i) {
    if (i < 0)  i = -1 - i;
    if (i >= N) i = 2 * N - 1 - i;
    return i;
}

__global__ void __launch_bounds__(512, 3) k_all(const float* __restrict__ x,
                                                float* __restrict__ out)
{
    extern __shared__ float sm[];
    float* lo_s = sm;                      // [LOR][KS]
    float* hi_s = sm + LOR * KS;           // [TR][KS]
    float* lr_s = sm + (LOR + TR) * KS;    // [TR][KS]

    const int tx  = threadIdx.x;           // 0..127
    const int ty  = threadIdx.y;           // 0..3
    const int tid = ty * 128 + tx;
    const int img = blockIdx.y;
    const int R0  = blockIdx.x * TR;

    const float* ximg = x + (size_t)img * N * N;

    const float rl[8] = REC_LO_INIT;
    const float rh[8] = REC_HI_INIT;

    // ---------------- P0: row DWT of 28 data rows into smem ----------------
    // 128 threads per row; thread tx produces k = 2tx, 2tx+1 from window
    // x[4tx-6 .. 4tx+3] (f2 + 2x f4 at 16B thread stride: near-dense lines).
    // 7 static bodies (rows ty, ty+4, ..., ty+24) -> ptxas batches the LDGs.
    {
        auto body = [&](int i) {
            const int gr = mirN(R0 - 6 + i);
            const float* xr = ximg + (size_t)gr * N;
            const bool own = (i >= 6) && (i < 6 + TR);
            float* lo = lo_s + i * KS;
            float* hi = hi_s + (i - 6) * KS;

            float win[10];
            if (tx >= 2) {
                const float2 f2 = *(const float2*)(xr + 4 * tx - 6);
                const float4 fa = *(const float4*)(xr + 4 * tx - 4);
                const float4 fb = *(const float4*)(xr + 4 * tx);
                win[0] = f2.x; win[1] = f2.y;
                win[2] = fa.x; win[3] = fa.y; win[4] = fa.z; win[5] = fa.w;
                win[6] = fb.x; win[7] = fb.y; win[8] = fb.z; win[9] = fb.w;
            } else {
#pragma unroll
                for (int u = 0; u < 10; ++u)
                    win[u] = xr[mirN(4 * tx - 6 + u)];
            }

            float a0 = 0.f, a1 = 0.f;
#pragma unroll
            for (int u = 0; u < 8; ++u) {
                a0 = fmaf(win[u],     rl[u], a0);
                a1 = fmaf(win[u + 2], rl[u], a1);
            }
            *(float2*)(lo + 2 * tx) = make_float2(a0, a1);

            if (own) {
                float d0 = 0.f, d1 = 0.f;
#pragma unroll
                for (int u = 0; u < 8; ++u) {
                    d0 = fmaf(win[u],     rh[u], d0);
                    d1 = fmaf(win[u + 2], rh[u], d1);
                }
                *(float2*)(hi + 2 * tx) = make_float2(d0, d1);
            }

            if (tx >= 125) {                       // tail k = 256..258
                const int kk = tx + 131;
                const int e0 = 2 * kk - 6;
                float aa = 0.f, dd = 0.f;
#pragma unroll
                for (int u = 0; u < 8; ++u) {
                    const float v = xr[mirN(e0 + u)];
                    aa = fmaf(v, rl[u], aa);
                    dd = fmaf(v, rh[u], dd);
                }
                lo[kk] = aa;
                if (own) hi[kk] = dd;
            }
        };

        body(ty);
        body(ty + 4);
        body(ty + 8);
        body(ty + 12);
        body(ty + 16);
        body(ty + 20);
        body(ty + 24);
    }
    __syncthreads();

    const int h = tid >> 8;                        // 0..1 (half id)

    // ------- P1: fused column correction, 14-tap, 8-row half-groups --------
    // half h owns output rows 8h..8h+7 of each column via a 20-row register
    // window (rows 8h..8h+19). Columns k = (tid&255), +256 tail.
    {
        const float WE[14] = { we_at(0),  we_at(1),  we_at(2),  we_at(3),
                               we_at(4),  we_at(5),  we_at(6),  we_at(7),
                               we_at(8),  we_at(9),  we_at(10), we_at(11),
                               we_at(12), we_at(13) };
        const float WO[14] = { wo_at(0),  wo_at(1),  wo_at(2),  wo_at(3),
                               wo_at(4),  wo_at(5),  wo_at(6),  wo_at(7),
                               wo_at(8),  wo_at(9),  wo_at(10), wo_at(11),
                               wo_at(12), wo_at(13) };
        const int c0 = tid & 255;              // 0..255
        for (int k = c0; k < M; k += 256) {
            float w[20];
#pragma unroll
            for (int i = 0; i < 20; ++i)
                w[i] = lo_s[(8 * h + i) * KS + k];
#pragma unroll
            for (int q = 0; q < 4; ++q) {      // output rows 8h+2q, 8h+2q+1
                float e = 0.f, o = 0.f;
#pragma unroll
                for (int m = 0; m < 14; ++m) {
                    e = fmaf(w[2 * q + m], WE[m], e);
                    o = fmaf(w[2 * q + m], WO[m], o);
                }
                lr_s[(8 * h + 2 * q)     * KS + k] = e;
                lr_s[(8 * h + 2 * q + 1) * KS + k] = o;
            }
        }
    }
    // Half-scoped barrier: half h's P2 consumes only rows 8h..8h+7 of lr_s
    // (produced by the same half) and hi_s (covered by the P0 barrier).
    asm volatile("bar.sync %0, %1;" :: "r"(1 + h), "r"(256) : "memory");

    // ------- P2: row IDWT to out, packed f32x2 (ev,od) pairs ---------------
    // half h handles rows 8h + rg2 and 8h + rg2 + 4 (rg2 = (tid&255)>>6).
    {
        const float rh2[8] = REC_HI2_INIT;
        const int local = tid & 255;
        const int jj  = local & 63;         // cols 8jj..8jj+7, u0 = 4jj
        const int rg2 = local >> 6;         // 0..3
        float* out_img = out + (size_t)img * N * N;

        auto body2 = [&](int tt) {
            const float* ar = lr_s + tt * KS + 4 * jj;
            const float* hr = hi_s + tt * KS + 4 * jj;
            const float4 a03 = *(const float4*)ar;
            const float2 a45 = *(const float2*)(ar + 4);
            const float  a6  = ar[6];
            const float4 d03 = *(const float4*)hr;
            const float2 d45 = *(const float2*)(hr + 4);
            const float  d6  = hr[6];
            const float a[7] = { a03.x, a03.y, a03.z, a03.w, a45.x, a45.y, a6 };
            const float d[7] = { d03.x, d03.y, d03.z, d03.w, d45.x, d45.y, d6 };

            unsigned long long o2[4];
#pragma unroll
            for (int p = 0; p < 4; ++p) {
                unsigned long long acc = 0ull;
#pragma unroll
                for (int i = 0; i < 4; ++i) {
                    fma2(acc, pk2(a[p + i], a[p + i]),
                              pk2(rl[6 - 2 * i],  rl[7 - 2 * i]));
                    fma2(acc, pk2(d[p + i], d[p + i]),
                              pk2(rh2[6 - 2 * i], rh2[7 - 2 * i]));
                }
                o2[p] = acc;
            }

            char* orow = (char*)(out_img + (size_t)(R0 + tt) * N + 8 * jj);
            *(ulonglong2*)(orow)      = make_ulonglong2(o2[0], o2[1]);
            *(ulonglong2*)(orow + 16) = make_ulonglong2(o2[2], o2[3]);
        };

        body2(8 * h + rg2);
        body2(8 * h + rg2 + 4);
    }
}

// ---------------------------------------------------------------------------
extern "C" void kernel_launch(void* const* d_in, const int* in_sizes, int n_in,
                              void* d_out, int out_size)
{
    const float* data = (const float*)d_in[0];
    float* out = (float*)d_out;
    (void)in_sizes; (void)n_in; (void)out_size;

    const int smem = (LOR + 2 * TR) * KS * (int)sizeof(float);  // 62400 B
    cudaFuncSetAttribute(k_all, cudaFuncAttributeMaxDynamicSharedMemorySize,
                         smem);

    k_all<<<dim3(N / TR, NIMG), dim3(128, 4), smem>>>(data, out);
}

// round 14
// speedup vs baseline: 1.0474x; 1.0474x over previous
#include <cuda_runtime.h>
#include <stdint.h>

// ---------------------------------------------------------------------------
// extract_high_freq via db4 wavelet, [96][512][512] fp32 — single fused kernel.
// TR=32 rows per block, 1024 threads, 2 CTA/SM (100% occupancy target).
//   P0: lo_s[i] = row-DWT-approx(data[mir(R0-6+i)]); hi_s for own rows
//   P1: lr_s[tt] = 14-tap column conv of lo_s (fused detail+synthesis+identity)
//   P2: out[t]   = row-IDWT(lr_s[tt], 2*hi_s[tt])   (packed f32x2)
// ---------------------------------------------------------------------------

#define N     512
#define M     259          // (512+7)/2
#define NIMG  96

#define TR    32           // output rows per block
#define LOR   (TR + 12)    // 44 lo rows: global [R0-6, R0+TR+5]
#define KS    260          // smem row stride (floats)
#define NTHR  1024

#define DL0 (-0.010597401784997278f)
#define DL1 ( 0.032883011666982945f)
#define DL2 ( 0.030841381835986965f)
#define DL3 (-0.18703481171888114f)
#define DL4 (-0.02798376941698385f)
#define DL5 ( 0.6308807679295904f)
#define DL6 ( 0.7148465705525415f)
#define DL7 ( 0.23037781330885523f)

// REC_LO[j] = DEC_LO[7-j] ; REC_HI[j] = (-1)^j * DEC_LO[j]
#define REC_LO_INIT  { DL7,  DL6,  DL5,  DL4,  DL3,  DL2,  DL1,  DL0 }
#define REC_HI_INIT  { DL0, -DL1,  DL2, -DL3,  DL4, -DL5,  DL6, -DL7 }
#define REC_HI2_INIT { 2*DL0, -2*DL1, 2*DL2, -2*DL3, 2*DL4, -2*DL5, 2*DL6, -2*DL7 }

// Combined column-correction weights (detail ∘ synthesis + identity).
__host__ __device__ constexpr float rh_at(int j) {
    constexpr float rh[8] = REC_HI_INIT;
    return rh[j];
}
__host__ __device__ constexpr float we_at(int m) {  // even t: rows tt..tt+13
    float s = (m == 6) ? 1.0f : 0.0f;
    for (int i = 0; i < 4; ++i) {
        const int j = m - 2 * i;
        if (j >= 0 && j < 8) s += rh_at(6 - 2 * i) * rh_at(j);
    }
    return s;
}
__host__ __device__ constexpr float wo_at(int m) {  // odd t: rows tt-1..tt+12
    float s = (m == 7) ? 1.0f : 0.0f;
    for (int i = 0; i < 4; ++i) {
        const int j = m - 2 * i;
        if (j >= 0 && j < 8) s += rh_at(7 - 2 * i) * rh_at(j);
    }
    return s;
}

// packed f32x2 helpers (sm_100+)
__device__ __forceinline__ unsigned long long pk2(float lo, float hi) {
    unsigned long long r;
    asm("mov.b64 %0, {%1, %2};" : "=l"(r) : "f"(lo), "f"(hi));
    return r;
}
__device__ __forceinline__ void fma2(unsigned long long& d,
                                     unsigned long long a,
                                     unsigned long long b) {
    asm("fma.rn.f32x2 %0, %1, %2, %3;" : "=l"(d) : "l"(a), "l"(b), "l"(d));
}

__device__ __forceinline__ int mirN(int i) {
    if (i < 0)  i = -1 - i;
    if (i >= N) i = 2 * N - 1 - i;
    return i;
}

__global__ void __launch_bounds__(NTHR, 2) k_all(const float* __restrict__ x,
                                                 float* __restrict__ out)
{
    extern __shared__ float sm[];
    float* lo_s = sm;                      // [LOR][KS]
    float* hi_s = sm + LOR * KS;           // [TR][KS]
    float* lr_s = sm + (LOR + TR) * KS;    // [TR][KS]

    const int tid = threadIdx.x;           // 0..1023
    const int img = blockIdx.y;
    const int R0  = blockIdx.x * TR;

    const float* ximg = x + (size_t)img * N * N;

    const float rl[8] = REC_LO_INIT;
    const float rh[8] = REC_HI_INIT;

    // ---------------- P0: row DWT of 44 data rows into smem ----------------
    // 16 gangs of 64 threads; gang rg handles rows rg, rg+16 (+rg+32 if
    // rg<12). Thread jj covers k = 4jj..4jj+3 from window x[8jj-6 .. 8jj+7].
    {
        const int jj = tid & 63;           // k = 4jj..4jj+3
        const int rg = tid >> 6;           // 0..15

        auto body = [&](int i) {
            const int gr = mirN(R0 - 6 + i);
            const float* xr = ximg + (size_t)gr * N;
            const bool own = (i >= 6) && (i < 6 + TR);
            float* lo = lo_s + i * KS;
            float* hi = hi_s + (i - 6) * KS;

            if (jj >= 1) {
                const float2 w0 = *(const float2*)(xr + 8 * jj - 6);
                const float4 w1 = *(const float4*)(xr + 8 * jj - 4);
                const float4 w2 = *(const float4*)(xr + 8 * jj);
                const float4 w3 = *(const float4*)(xr + 8 * jj + 4);
                const float win[14] = { w0.x, w0.y,
                                        w1.x, w1.y, w1.z, w1.w,
                                        w2.x, w2.y, w2.z, w2.w,
                                        w3.x, w3.y, w3.z, w3.w };
                float a[4];
#pragma unroll
                for (int q = 0; q < 4; ++q) {
                    float aa = 0.f;
#pragma unroll
                    for (int u = 0; u < 8; ++u)
                        aa = fmaf(win[2 * q + u], rl[u], aa);
                    a[q] = aa;
                }
                *(float4*)(lo + 4 * jj) = make_float4(a[0], a[1], a[2], a[3]);
                if (own) {
                    float d[4];
#pragma unroll
                    for (int q = 0; q < 4; ++q) {
                        float dd = 0.f;
#pragma unroll
                        for (int u = 0; u < 8; ++u)
                            dd = fmaf(win[2 * q + u], rh[u], dd);
                        d[q] = dd;
                    }
                    *(float4*)(hi + 4 * jj) = make_float4(d[0], d[1], d[2], d[3]);
                }
            } else {
                float a[4], d[4];
#pragma unroll
                for (int q = 0; q < 4; ++q) {
                    const int e0 = 2 * q - 6;
                    float aa = 0.f, dd = 0.f;
#pragma unroll
                    for (int u = 0; u < 8; ++u) {
                        const float v = xr[mirN(e0 + u)];
                        aa = fmaf(v, rl[u], aa);
                        dd = fmaf(v, rh[u], dd);
                    }
                    a[q] = aa; d[q] = dd;
                }
                *(float4*)(lo) = make_float4(a[0], a[1], a[2], a[3]);
                if (own)
                    *(float4*)(hi) = make_float4(d[0], d[1], d[2], d[3]);
            }

            if (jj >= 1 && jj <= 3) {                // tail k = 256..258
                const int kk = 255 + jj;
                const int e0 = 2 * kk - 6;
                float aa = 0.f, dd = 0.f;
#pragma unroll
                for (int u = 0; u < 8; ++u) {
                    const float v = xr[mirN(e0 + u)];
                    aa = fmaf(v, rl[u], aa);
                    dd = fmaf(v, rh[u], dd);
                }
                lo[kk] = aa;
                if (own) hi[kk] = dd;
            }
        };

        body(rg);
        body(rg + 16);
        if (rg < LOR - 32) body(rg + 32);            // rg < 12
    }
    __syncthreads();

    const int qh = tid >> 8;                         // quarter id 0..3

    // ------- P1: fused column correction, 14-tap, 8-row quarter groups -----
    // quarter qh owns output rows 8qh..8qh+7 via a 20-row register window
    // (rows 8qh..8qh+19). Columns k = (tid&255), +256 tail.
    {
        const float WE[14] = { we_at(0),  we_at(1),  we_at(2),  we_at(3),
                               we_at(4),  we_at(5),  we_at(6),  we_at(7),
                               we_at(8),  we_at(9),  we_at(10), we_at(11),
                               we_at(12), we_at(13) };
        const float WO[14] = { wo_at(0),  wo_at(1),  wo_at(2),  wo_at(3),
                               wo_at(4),  wo_at(5),  wo_at(6),  wo_at(7),
                               wo_at(8),  wo_at(9),  wo_at(10), wo_at(11),
                               wo_at(12), wo_at(13) };
        const int c0 = tid & 255;              // 0..255
        const int rbase = 8 * qh;
        for (int k = c0; k < M; k += 256) {
            float w[20];
#pragma unroll
            for (int i = 0; i < 20; ++i)
                w[i] = lo_s[(rbase + i) * KS + k];
#pragma unroll
            for (int q = 0; q < 4; ++q) {      // output rows rbase+2q, +2q+1
                float e = 0.f, o = 0.f;
#pragma unroll
                for (int m = 0; m < 14; ++m) {
                    e = fmaf(w[2 * q + m], WE[m], e);
                    o = fmaf(w[2 * q + m], WO[m], o);
                }
                lr_s[(rbase + 2 * q)     * KS + k] = e;
                lr_s[(rbase + 2 * q + 1) * KS + k] = o;
            }
        }
    }
    // Quarter-scoped barrier: quarter qh's P2 consumes only lr rows
    // 8qh..8qh+7 (produced by this quarter) and hi_s (P0 barrier covers it).
    asm volatile("bar.sync %0, %1;" :: "r"(1 + qh), "r"(256) : "memory");

    // ------- P2: row IDWT to out, packed f32x2 (ev,od) pairs ---------------
    // quarter qh handles rows 8qh + rg2 and 8qh + rg2 + 4 (rg2=(tid&255)>>6).
    {
        const float rh2[8] = REC_HI2_INIT;
        const int local = tid & 255;
        const int jj  = local & 63;         // cols 8jj..8jj+7, u0 = 4jj
        const int rg2 = local >> 6;         // 0..3
        float* out_img = out + (size_t)img * N * N;

        auto body2 = [&](int tt) {
            const float* ar = lr_s + tt * KS + 4 * jj;
            const float* hr = hi_s + tt * KS + 4 * jj;
            const float4 a03 = *(const float4*)ar;
            const float2 a45 = *(const float2*)(ar + 4);
            const float  a6  = ar[6];
            const float4 d03 = *(const float4*)hr;
            const float2 d45 = *(const float2*)(hr + 4);
            const float  d6  = hr[6];
            const float a[7] = { a03.x, a03.y, a03.z, a03.w, a45.x, a45.y, a6 };
            const float d[7] = { d03.x, d03.y, d03.z, d03.w, d45.x, d45.y, d6 };

            unsigned long long o2[4];
#pragma unroll
            for (int p = 0; p < 4; ++p) {
                unsigned long long acc = 0ull;
#pragma unroll
                for (int i = 0; i < 4; ++i) {
                    fma2(acc, pk2(a[p + i], a[p + i]),
                              pk2(rl[6 - 2 * i],  rl[7 - 2 * i]));
                    fma2(acc, pk2(d[p + i], d[p + i]),
                              pk2(rh2[6 - 2 * i], rh2[7 - 2 * i]));
                }
                o2[p] = acc;
            }

            char* orow = (char*)(out_img + (size_t)(R0 + tt) * N + 8 * jj);
            *(ulonglong2*)(orow)      = make_ulonglong2(o2[0], o2[1]);
            *(ulonglong2*)(orow + 16) = make_ulonglong2(o2[2], o2[3]);
        };

        body2(8 * qh + rg2);
        body2(8 * qh + rg2 + 4);
    }
}

// ---------------------------------------------------------------------------
extern "C" void kernel_launch(void* const* d_in, const int* in_sizes, int n_in,
                              void* d_out, int out_size)
{
    const float* data = (const float*)d_in[0];
    float* out = (float*)d_out;
    (void)in_sizes; (void)n_in; (void)out_size;

    const int smem = (LOR + 2 * TR) * KS * (int)sizeof(float);  // 112320 B
    cudaFuncSetAttribute(k_all, cudaFuncAttributeMaxDynamicSharedMemorySize,
                         smem);

    k_all<<<dim3(N / TR, NIMG), NTHR, smem>>>(data, out);
}

// round 15
// speedup vs baseline: 1.0815x; 1.0325x over previous
#include <cuda_runtime.h>
#include <stdint.h>

// ---------------------------------------------------------------------------
// extract_high_freq via db4 wavelet, [96][512][512] fp32 — single fused kernel.
//   P0: lo_s[i] = row-DWT-approx(data[mir(R0-6+i)]); hi_s for own rows
//   P1: lr_s[tt] = column correction, two-step in registers:
//       ds[j] = 8-tap detail of lo_s window; lr = lo + 4-tap synthesis(ds)
//   P2: out[t]  = row-IDWT(lr_s[tt], 2*hi_s[tt])   (packed f32x2)
// ---------------------------------------------------------------------------

#define N     512
#define M     259          // (512+7)/2
#define NIMG  96

#define TR    16           // output rows per block
#define LOR   28           // lo rows: global [R0-6, R0+21]
#define KS    260          // smem row stride (floats)

#define DL0 (-0.010597401784997278f)
#define DL1 ( 0.032883011666982945f)
#define DL2 ( 0.030841381835986965f)
#define DL3 (-0.18703481171888114f)
#define DL4 (-0.02798376941698385f)
#define DL5 ( 0.6308807679295904f)
#define DL6 ( 0.7148465705525415f)
#define DL7 ( 0.23037781330885523f)

// REC_LO[j] = DEC_LO[7-j] ; REC_HI[j] = (-1)^j * DEC_LO[j]
#define REC_LO_INIT  { DL7,  DL6,  DL5,  DL4,  DL3,  DL2,  DL1,  DL0 }
#define REC_HI_INIT  { DL0, -DL1,  DL2, -DL3,  DL4, -DL5,  DL6, -DL7 }
#define REC_HI2_INIT { 2*DL0, -2*DL1, 2*DL2, -2*DL3, 2*DL4, -2*DL5, 2*DL6, -2*DL7 }

// packed f32x2 helpers (sm_100+)
__device__ __forceinline__ unsigned long long pk2(float lo, float hi) {
    unsigned long long r;
    asm("mov.b64 %0, {%1, %2};" : "=l"(r) : "f"(lo), "f"(hi));
    return r;
}
__device__ __forceinline__ void fma2(unsigned long long& d,
                                     unsigned long long a,
                                     unsigned long long b) {
    asm("fma.rn.f32x2 %0, %1, %2, %3;" : "=l"(d) : "l"(a), "l"(b), "l"(d));
}

__device__ __forceinline__ int mirN(int i) {
    if (i < 0)  i = -1 - i;
    if (i >= N) i = 2 * N - 1 - i;
    return i;
}

__global__ void __launch_bounds__(512, 3) k_all(const float* __restrict__ x,
                                                float* __restrict__ out)
{
    extern __shared__ float sm[];
    float* lo_s = sm;                      // [LOR][KS]
    float* hi_s = sm + LOR * KS;           // [TR][KS]
    float* lr_s = sm + (LOR + TR) * KS;    // [TR][KS]

    const int tx  = threadIdx.x;           // 0..127
    const int ty  = threadIdx.y;           // 0..3
    const int tid = ty * 128 + tx;
    const int img = blockIdx.y;
    const int R0  = blockIdx.x * TR;

    const float* ximg = x + (size_t)img * N * N;

    const float rl[8] = REC_LO_INIT;
    const float rh[8] = REC_HI_INIT;

    // ---------------- P0: row DWT of 28 data rows into smem ----------------
    // 8 gangs of 64 threads; gang rg handles rows rg, rg+8, rg+16 (+rg+24 if
    // rg<4). Static call sites let ptxas batch the global loads (high MLP).
    {
        const int jj = tid & 63;           // k = 4jj..4jj+3
        const int rg = tid >> 6;           // 0..7

        auto body = [&](int i) {
            const int gr = mirN(R0 - 6 + i);
            const float* xr = ximg + (size_t)gr * N;
            const bool own = (i >= 6) && (i < 6 + TR);
            float* lo = lo_s + i * KS;
            float* hi = hi_s + (i - 6) * KS;

            if (jj >= 1) {
                const float2 w0 = *(const float2*)(xr + 8 * jj - 6);
                const float4 w1 = *(const float4*)(xr + 8 * jj - 4);
                const float4 w2 = *(const float4*)(xr + 8 * jj);
                const float4 w3 = *(const float4*)(xr + 8 * jj + 4);
                const float win[14] = { w0.x, w0.y,
                                        w1.x, w1.y, w1.z, w1.w,
                                        w2.x, w2.y, w2.z, w2.w,
                                        w3.x, w3.y, w3.z, w3.w };
                float a[4];
#pragma unroll
                for (int q = 0; q < 4; ++q) {
                    float aa = 0.f;
#pragma unroll
                    for (int u = 0; u < 8; ++u)
                        aa = fmaf(win[2 * q + u], rl[u], aa);
                    a[q] = aa;
                }
                *(float4*)(lo + 4 * jj) = make_float4(a[0], a[1], a[2], a[3]);
                if (own) {
                    float d[4];
#pragma unroll
                    for (int q = 0; q < 4; ++q) {
                        float dd = 0.f;
#pragma unroll
                        for (int u = 0; u < 8; ++u)
                            dd = fmaf(win[2 * q + u], rh[u], dd);
                        d[q] = dd;
                    }
                    *(float4*)(hi + 4 * jj) = make_float4(d[0], d[1], d[2], d[3]);
                }
            } else {
                float a[4], d[4];
#pragma unroll
                for (int q = 0; q < 4; ++q) {
                    const int e0 = 2 * q - 6;
                    float aa = 0.f, dd = 0.f;
#pragma unroll
                    for (int u = 0; u < 8; ++u) {
                        const float v = xr[mirN(e0 + u)];
                        aa = fmaf(v, rl[u], aa);
                        dd = fmaf(v, rh[u], dd);
                    }
                    a[q] = aa; d[q] = dd;
                }
                *(float4*)(lo) = make_float4(a[0], a[1], a[2], a[3]);
                if (own)
                    *(float4*)(hi) = make_float4(d[0], d[1], d[2], d[3]);
            }

            if (jj >= 1 && jj <= 3) {                // tail k = 256..258
                const int kk = 255 + jj;
                const int e0 = 2 * kk - 6;
                float aa = 0.f, dd = 0.f;
#pragma unroll
                for (int u = 0; u < 8; ++u) {
                    const float v = xr[mirN(e0 + u)];
                    aa = fmaf(v, rl[u], aa);
                    dd = fmaf(v, rh[u], dd);
                }
                lo[kk] = aa;
                if (own) hi[kk] = dd;
            }
        };

        body(rg);
        body(rg + 8);
        body(rg + 16);
        if (rg < 4) body(rg + 24);
    }
    __syncthreads();

    // ------- P1: column correction, two-step in registers ------------------
    // half h = tid>>8 owns output rows 8h..8h+7 of column k via a 20-row
    // register window w[0..19] (lo_s rows 8h..8h+19).
    //   ds[j]   = sum_m w[2j+m]*rh[m]                  (j = 0..6)
    //   lr[r]   = w[r+6] + sum_i ds[(r>>1)+i]*rh[{6,7}-2i]  (r = 0..7)
    {
        const int h  = tid >> 8;               // 0..1
        const int c0 = tid & 255;              // 0..255
        const int rbase = 8 * h;
        for (int k = c0; k < M; k += 256) {
            float w[20];
#pragma unroll
            for (int i = 0; i < 20; ++i)
                w[i] = lo_s[(rbase + i) * KS + k];

            float ds[7];
#pragma unroll
            for (int j = 0; j < 7; ++j) {
                float d = 0.f;
#pragma unroll
                for (int m = 0; m < 8; ++m)
                    d = fmaf(w[2 * j + m], rh[m], d);
                ds[j] = d;
            }

#pragma unroll
            for (int r = 0; r < 8; ++r) {      // output row rbase + r
                const int q0 = r >> 1;
                float acc;
                if ((r & 1) == 0) {
                    acc = fmaf(ds[q0],     rh[6], w[r + 6]);
                    acc = fmaf(ds[q0 + 1], rh[4], acc);
                    acc = fmaf(ds[q0 + 2], rh[2], acc);
                    acc = fmaf(ds[q0 + 3], rh[0], acc);
                } else {
                    acc = fmaf(ds[q0],     rh[7], w[r + 6]);
                    acc = fmaf(ds[q0 + 1], rh[5], acc);
                    acc = fmaf(ds[q0 + 2], rh[3], acc);
                    acc = fmaf(ds[q0 + 3], rh[1], acc);
                }
                lr_s[(rbase + r) * KS + k] = acc;
            }
        }
    }
    __syncthreads();

    // ------- P2: row IDWT to out, packed f32x2 (ev,od) pairs ---------------
    {
        const float rh2[8] = REC_HI2_INIT;
        const int jj = tid & 63;            // cols 8jj..8jj+7, u0 = 4jj
        const int rg = tid >> 6;            // 0..7; rows rg and rg+8
        float* out_img = out + (size_t)img * N * N;

        auto body2 = [&](int tt) {
            const float* ar = lr_s + tt * KS + 4 * jj;
            const float* hr = hi_s + tt * KS + 4 * jj;
            const float4 a03 = *(const float4*)ar;
            const float2 a45 = *(const float2*)(ar + 4);
            const float  a6  = ar[6];
            const float4 d03 = *(const float4*)hr;
            const float2 d45 = *(const float2*)(hr + 4);
            const float  d6  = hr[6];
            const float a[7] = { a03.x, a03.y, a03.z, a03.w, a45.x, a45.y, a6 };
            const float d[7] = { d03.x, d03.y, d03.z, d03.w, d45.x, d45.y, d6 };

            unsigned long long o2[4];
#pragma unroll
            for (int p = 0; p < 4; ++p) {
                unsigned long long acc = 0ull;
#pragma unroll
                for (int i = 0; i < 4; ++i) {
                    fma2(acc, pk2(a[p + i], a[p + i]),
                              pk2(rl[6 - 2 * i],  rl[7 - 2 * i]));
                    fma2(acc, pk2(d[p + i], d[p + i]),
                              pk2(rh2[6 - 2 * i], rh2[7 - 2 * i]));
                }
                o2[p] = acc;
            }

            char* orow = (char*)(out_img + (size_t)(R0 + tt) * N + 8 * jj);
            *(ulonglong2*)(orow)      = make_ulonglong2(o2[0], o2[1]);
            *(ulonglong2*)(orow + 16) = make_ulonglong2(o2[2], o2[3]);
        };

        body2(rg);
        body2(rg + 8);
    }
}

// ---------------------------------------------------------------------------
extern "C" void kernel_launch(void* const* d_in, const int* in_sizes, int n_in,
                              void* d_out, int out_size)
{
    const float* data = (const float*)d_in[0];
    float* out = (float*)d_out;
    (void)in_sizes; (void)n_in; (void)out_size;

    const int smem = (LOR + 2 * TR) * KS * (int)sizeof(float);  // 62400 B
    cudaFuncSetAttribute(k_all, cudaFuncAttributeMaxDynamicSharedMemorySize,
                         smem);

    k_all<<<dim3(N / TR, NIMG), dim3(128, 4), smem>>>(data, out);
}